// round 15
// baseline (speedup 1.0000x reference)
#include <cuda_runtime.h>
#include <math.h>
#include <stdint.h>

#define NN  50000
#define FINF 64
#define HH  128
#define EE  800000
#define TT  8
#define PP  250000
#define DD  500000
#define GG  20000
#define VV  2000
#define CATW 384

// ---------------- scratch (device globals; no allocation allowed) ----------------
__device__ __align__(16) float  g_feats[(size_t)(TT + 1) * NN * HH];
__device__ __align__(16) float  g_agg[(size_t)NN * HH];
__device__ __align__(16) float  g_dstf[(size_t)PP * HH];
__device__ float  g_logprob[PP * 2];
__device__ double g_gsum[GG * 2];
__device__ float  g_within[GG * 2];
__device__ int    g_deg[NN];
__device__ float  g_invdeg[NN];
__device__ int    g_rowptr[NN + 1];
__device__ int    g_cursor[NN];
__device__ int    g_csr[EE];
__device__ int    g_vstart[VV];
__device__ float  g_logc[VV];
__device__ int    g_dstart[PP + 1];
__device__ int    g_gstart[GG + 1];

// ---------------- packed fp32x2 helpers ----------------
__device__ __forceinline__ unsigned long long pk2(float lo, float hi) {
    unsigned long long r;
    asm("mov.b64 %0, {%1, %2};" : "=l"(r) : "f"(lo), "f"(hi));
    return r;
}
__device__ __forceinline__ void upk2(unsigned long long v, float& lo, float& hi) {
    asm("mov.b64 {%0, %1}, %2;" : "=f"(lo), "=f"(hi) : "l"(v));
}
#define FFMA2(c, a, b) \
    asm("fma.rn.f32x2 %0, %1, %2, %3;" : "=l"(c) : "l"(a), "l"(b), "l"(c))

#define BSTR 132
#define BK   32

// per-k-step compute (round-9 proven form)
#define K_STEP(Asb, Bsb, kk)                                                    \
    do {                                                                        \
        float4 a0 = *(const float4*)&(Asb)[kk][rowBase];                        \
        float4 a1 = *(const float4*)&(Asb)[kk][rowBase + 4];                    \
        float4 b0 = *(const float4*)&(Bsb)[kk][colBase];                        \
        float4 b1 = *(const float4*)&(Bsb)[kk][colBase + 4];                    \
        unsigned long long rbp[4];                                              \
        rbp[0] = pk2(b0.x, b0.y);                                               \
        rbp[1] = pk2(b0.z, b0.w);                                               \
        rbp[2] = pk2(b1.x, b1.y);                                               \
        rbp[3] = pk2(b1.z, b1.w);                                               \
        float ra[8] = {a0.x, a0.y, a0.z, a0.w, a1.x, a1.y, a1.z, a1.w};         \
        _Pragma("unroll")                                                       \
        for (int i = 0; i < 8; i++) {                                           \
            unsigned long long rai = pk2(ra[i], ra[i]);                         \
            _Pragma("unroll")                                                   \
            for (int j = 0; j < 4; j++) FFMA2(acc2[i][j], rai, rbp[j]);         \
        }                                                                       \
    } while (0)

// ---------------- CSR build ----------------
__global__ void k_count_deg(const int* __restrict__ edge_dst) {
    int e = blockIdx.x * blockDim.x + threadIdx.x;
    if (e < EE) atomicAdd(&g_deg[edge_dst[e]], 1);
}

__global__ void k_scan() {
    __shared__ int warpsum[32];
    __shared__ int s_carry;
    if (threadIdx.x == 0) s_carry = 0;
    __syncthreads();
    int lane = threadIdx.x & 31, w = threadIdx.x >> 5;
    for (int base = 0; base < NN; base += 1024) {
        int i = base + threadIdx.x;
        int v = (i < NN) ? g_deg[i] : 0;
        int s = v;
#pragma unroll
        for (int o = 1; o < 32; o <<= 1) {
            int t = __shfl_up_sync(0xffffffffu, s, o);
            if (lane >= o) s += t;
        }
        if (lane == 31) warpsum[w] = s;
        __syncthreads();
        if (w == 0) {
            int ws = warpsum[lane];
#pragma unroll
            for (int o = 1; o < 32; o <<= 1) {
                int t = __shfl_up_sync(0xffffffffu, ws, o);
                if (lane >= o) ws += t;
            }
            warpsum[lane] = ws;
        }
        __syncthreads();
        int incl = s + (w > 0 ? warpsum[w - 1] : 0) + s_carry;
        if (i < NN) {
            g_rowptr[i + 1] = incl;
            g_cursor[i] = incl - v;
            g_invdeg[i] = 1.0f / (float)(v > 1 ? v : 1);
            if (i == 0) g_rowptr[0] = 0;
        }
        __syncthreads();
        if (threadIdx.x == 1023) s_carry = incl;
        __syncthreads();
    }
}

__global__ void k_fill(const int* __restrict__ edge_src, const int* __restrict__ edge_dst) {
    int e = blockIdx.x * blockDim.x + threadIdx.x;
    if (e >= EE) return;
    int pos = atomicAdd(&g_cursor[edge_dst[e]], 1);
    g_csr[pos] = edge_src[e];
}

// ---------------- mean aggregation (atomic-free via CSR, float4) ----------------
template <int F>
__global__ void k_aggregate4(const float* __restrict__ h) {
    int node = blockIdx.x * blockDim.y + threadIdx.y;
    if (node >= NN) return;
    int f4 = threadIdx.x;
    int e0 = g_rowptr[node], e1 = g_rowptr[node + 1];
    float4 s = make_float4(0.f, 0.f, 0.f, 0.f);
    for (int e = e0; e < e1; e++) {
        int src = g_csr[e];
        float4 v = *(const float4*)(h + (size_t)src * F + f4 * 4);
        s.x += v.x; s.y += v.y; s.z += v.z; s.w += v.w;
    }
    float id = g_invdeg[node];
    s.x *= id; s.y *= id; s.z *= id; s.w *= id;
    *(float4*)(g_agg + (size_t)node * F + f4 * 4) = s;
}

// ---------------- MP GEMM: C = relu(A1@W1 + A2@W2 + bias), BK=32 -----------------
__global__ __launch_bounds__(256, 2) void k_sgemm_dual(
    const float* __restrict__ A1, int K1,
    const float* __restrict__ A2, int K2,
    const float* __restrict__ W1, const float* __restrict__ W2,
    const float* __restrict__ bias,
    float* __restrict__ C, int M, int NC)
{
    __shared__ __align__(16) float As[2][BK][BSTR];
    __shared__ __align__(16) float Bs[2][BK][BSTR];
    int tid = threadIdx.x;
    int rowBlock = blockIdx.y * 128;
    int colBlock = blockIdx.x * 128;
    int tx = tid & 15, ty = tid >> 4;
    int rowBase = ty * 8, colBase = tx * 8;

    // loader geometry: 4 float4 each for A and B per thread.
    // A: one row per thread (slots 4t..4t+3 share row), k-offsets (tid&1)*16 + 4i
    int la_r = tid >> 1;
    int la_kb = (tid & 1) * 16;
    int lb_r[4], lb_n[4];
#pragma unroll
    for (int i = 0; i < 4; i++) {
        int slot = tid * 4 + i;
        lb_r[i] = slot >> 5;           // 0..31
        lb_n[i] = (slot & 31) * 4;     // 0..124
    }

    unsigned long long acc2[8][4];
#pragma unroll
    for (int i = 0; i < 8; i++)
#pragma unroll
        for (int j = 0; j < 4; j++) acc2[i][j] = 0ull;

    int nt1 = K1 >> 5;
    int nt = nt1 + (K2 >> 5);

    int gmr = rowBlock + la_r;
    bool mok = gmr < M;

    float4 av[4], bv[4];
#pragma unroll
    for (int i = 0; i < 4; i++) {
        av[i] = mok ? *(const float4*)(A1 + (size_t)gmr * K1 + la_kb + i * 4)
                    : make_float4(0.f, 0.f, 0.f, 0.f);
        bv[i] = *(const float4*)(W1 + (size_t)lb_r[i] * NC + colBlock + lb_n[i]);
    }
#pragma unroll
    for (int i = 0; i < 4; i++) {
        As[0][la_kb + i * 4 + 0][la_r] = av[i].x;
        As[0][la_kb + i * 4 + 1][la_r] = av[i].y;
        As[0][la_kb + i * 4 + 2][la_r] = av[i].z;
        As[0][la_kb + i * 4 + 3][la_r] = av[i].w;
        *(float4*)&Bs[0][lb_r[i]][lb_n[i]] = bv[i];
    }
    __syncthreads();

    int s = 0;
#pragma unroll 1
    for (int t = 0; t < nt; t++) {
        if (t + 1 < nt) {
            int tn = t + 1;
            const float* A; const float* W; int K; int k0;
            if (tn < nt1) { A = A1; W = W1; K = K1; k0 = tn * BK; }
            else          { A = A2; W = W2; K = K2; k0 = (tn - nt1) * BK; }
#pragma unroll
            for (int i = 0; i < 4; i++) {
                av[i] = mok ? *(const float4*)(A + (size_t)gmr * K + k0 + la_kb + i * 4)
                            : make_float4(0.f, 0.f, 0.f, 0.f);
                bv[i] = *(const float4*)(W + (size_t)(k0 + lb_r[i]) * NC + colBlock + lb_n[i]);
            }
        }
#pragma unroll
        for (int k = 0; k < BK; k++) K_STEP(As[s], Bs[s], k);
        if (t + 1 < nt) {
            int sn = s ^ 1;
#pragma unroll
            for (int i = 0; i < 4; i++) {
                As[sn][la_kb + i * 4 + 0][la_r] = av[i].x;
                As[sn][la_kb + i * 4 + 1][la_r] = av[i].y;
                As[sn][la_kb + i * 4 + 2][la_r] = av[i].z;
                As[sn][la_kb + i * 4 + 3][la_r] = av[i].w;
                *(float4*)&Bs[sn][lb_r[i]][lb_n[i]] = bv[i];
            }
        }
        __syncthreads();
        s ^= 1;
    }

    float4 bb0 = *(const float4*)(bias + colBlock + colBase);
    float4 bb1 = *(const float4*)(bias + colBlock + colBase + 4);
    float bbs[8] = {bb0.x, bb0.y, bb0.z, bb0.w, bb1.x, bb1.y, bb1.z, bb1.w};
#pragma unroll
    for (int i = 0; i < 8; i++) {
        int gm = rowBlock + rowBase + i;
        if (gm >= M) continue;
        float o[8];
#pragma unroll
        for (int j = 0; j < 4; j++) upk2(acc2[i][j], o[j * 2], o[j * 2 + 1]);
#pragma unroll
        for (int j = 0; j < 8; j++) o[j] = fmaxf(o[j] + bbs[j], 0.f);
        float* cp = C + (size_t)gm * NC + colBlock + colBase;
        *(float4*)cp       = make_float4(o[0], o[1], o[2], o[3]);
        *(float4*)(cp + 4) = make_float4(o[4], o[5], o[6], o[7]);
    }
}

// ---------------- fused decoder: 3 col-blocks/CTA, BK=32, SMEM logit accum -------
__global__ __launch_bounds__(256, 2) void k_gemm_dec(
    const float* __restrict__ Wd1, const float* __restrict__ bd1,
    const float* __restrict__ Wd2, const float* __restrict__ bd2,
    const int* __restrict__ place_idx, const int* __restrict__ src_idx,
    const int* __restrict__ t_idx)
{
    extern __shared__ __align__(16) float dsm[];
    float (*As)[BK][BSTR] = (float (*)[BK][BSTR])dsm;                   // 2*BK*BSTR
    float (*Bs)[BK][BSTR] = (float (*)[BK][BSTR])(dsm + 2 * BK * BSTR);
    float2 (*red)[17] = (float2 (*)[17])(dsm + 4 * BK * BSTR);          // [128][17]

    int tid = threadIdx.x;
    int rowBlock = blockIdx.x * 128;
    int tx = tid & 15, ty = tid >> 4;
    int rowBase = ty * 8, colBase = tx * 8;

    int la_r = tid >> 1;
    int la_kb = (tid & 1) * 16;
    int lb_r[4], lb_n[4];
#pragma unroll
    for (int i = 0; i < 4; i++) {
        int slot = tid * 4 + i;
        lb_r[i] = slot >> 5;
        lb_n[i] = (slot & 31) * 4;
    }

#pragma unroll
    for (int i = tid; i < 128 * 17; i += 256)
        ((float2*)red)[i] = make_float2(0.f, 0.f);

    // per-thread gather bases (one A row per thread)
    int gp = rowBlock + la_r;
    bool mok = gp < PP;
    const float* ap[3];
    {
        int pidx = mok ? gp : 0;
        int t = __ldg(t_idx + pidx);
        ap[0] = g_feats + ((size_t)t * NN + __ldg(place_idx + pidx)) * HH;
        ap[1] = g_feats + ((size_t)t * NN + __ldg(src_idx + pidx)) * HH;
        ap[2] = g_dstf + (size_t)pidx * HH;
    }

    const int nt = CATW / BK;  // 12 tiles per col-block

#pragma unroll 1
    for (int cb = 0; cb < 3; cb++) {
        int colBlock = cb * 128;

        unsigned long long acc2[8][4];
#pragma unroll
        for (int i = 0; i < 8; i++)
#pragma unroll
            for (int j = 0; j < 4; j++) acc2[i][j] = 0ull;

        float4 av[4], bv[4];
#pragma unroll
        for (int i = 0; i < 4; i++) {
            av[i] = mok ? *(const float4*)(ap[0] + la_kb + i * 4)
                        : make_float4(0.f, 0.f, 0.f, 0.f);
            bv[i] = *(const float4*)(Wd1 + (size_t)lb_r[i] * CATW + colBlock + lb_n[i]);
        }
#pragma unroll
        for (int i = 0; i < 4; i++) {
            As[0][la_kb + i * 4 + 0][la_r] = av[i].x;
            As[0][la_kb + i * 4 + 1][la_r] = av[i].y;
            As[0][la_kb + i * 4 + 2][la_r] = av[i].z;
            As[0][la_kb + i * 4 + 3][la_r] = av[i].w;
            *(float4*)&Bs[0][lb_r[i]][lb_n[i]] = bv[i];
        }
        __syncthreads();

        int s = 0;
#pragma unroll 1
        for (int t = 0; t < nt; t++) {
            if (t + 1 < nt) {
                int k0 = (t + 1) * BK;
                int seg = k0 >> 7, koff = k0 & 127;
#pragma unroll
                for (int i = 0; i < 4; i++) {
                    av[i] = mok ? *(const float4*)(ap[seg] + koff + la_kb + i * 4)
                                : make_float4(0.f, 0.f, 0.f, 0.f);
                    bv[i] = *(const float4*)(Wd1 + (size_t)(k0 + lb_r[i]) * CATW + colBlock + lb_n[i]);
                }
            }
#pragma unroll
            for (int k = 0; k < BK; k++) K_STEP(As[s], Bs[s], k);
            if (t + 1 < nt) {
                int sn = s ^ 1;
#pragma unroll
                for (int i = 0; i < 4; i++) {
                    As[sn][la_kb + i * 4 + 0][la_r] = av[i].x;
                    As[sn][la_kb + i * 4 + 1][la_r] = av[i].y;
                    As[sn][la_kb + i * 4 + 2][la_r] = av[i].z;
                    As[sn][la_kb + i * 4 + 3][la_r] = av[i].w;
                    *(float4*)&Bs[sn][lb_r[i]][lb_n[i]] = bv[i];
                }
            }
            __syncthreads();
            s ^= 1;
        }

        float4 bb0 = *(const float4*)(bd1 + colBlock + colBase);
        float4 bb1 = *(const float4*)(bd1 + colBlock + colBase + 4);
        float bbs[8] = {bb0.x, bb0.y, bb0.z, bb0.w, bb1.x, bb1.y, bb1.z, bb1.w};
        float w20[8], w21[8];
#pragma unroll
        for (int j = 0; j < 8; j++) {
            float2 w = *(const float2*)(Wd2 + (colBlock + colBase + j) * 2);
            w20[j] = w.x; w21[j] = w.y;
        }
#pragma unroll
        for (int i = 0; i < 8; i++) {
            float o[8];
#pragma unroll
            for (int j = 0; j < 4; j++) upk2(acc2[i][j], o[j * 2], o[j * 2 + 1]);
            float pa0 = 0.f, pa1 = 0.f;
#pragma unroll
            for (int j = 0; j < 8; j++) {
                float h = fmaxf(o[j] + bbs[j], 0.f);
                pa0 += h * w20[j];
                pa1 += h * w21[j];
            }
            float2 cur = red[rowBase + i][tx];
            red[rowBase + i][tx] = make_float2(cur.x + pa0, cur.y + pa1);
        }
        __syncthreads();
    }

    if (tid < 128) {
        int p = rowBlock + tid;
        if (p < PP) {
            float s0 = 0.f, s1 = 0.f;
#pragma unroll
            for (int c = 0; c < 16; c++) {
                float2 v = red[tid][c];
                s0 += v.x; s1 += v.y;
            }
            float a0 = s0 + bd2[0];
            float a1 = s1 + bd2[1];
            float m = fmaxf(a0, a1);
            float lse = m + logf(expf(a0 - m) + expf(a1 - m));
            g_logprob[p * 2]     = a0 - lse;
            g_logprob[p * 2 + 1] = a1 - lse;
        }
    }
}

#define DEC_SMEM ((4 * BK * BSTR + 128 * 17 * 2) * 4)

// ---------------- dst segment-sum (atomic-free; dst_seg is sorted) ----------------
__global__ void k_dst_bounds(const int* __restrict__ dst_seg) {
    int p = blockIdx.x * blockDim.x + threadIdx.x;
    if (p > PP) return;
    int lo = 0, hi = DD;
    while (lo < hi) {
        int mid = (lo + hi) >> 1;
        if (dst_seg[mid] < p) lo = mid + 1; else hi = mid;
    }
    g_dstart[p] = lo;
}

__global__ void k_dst_sum(const int* __restrict__ dst_nodes, const int* __restrict__ t_idx) {
    int idx = blockIdx.x * blockDim.x + threadIdx.x;
    if (idx >= PP * 32) return;
    int p = idx >> 5, q = idx & 31;
    int e0 = g_dstart[p], e1 = g_dstart[p + 1];
    const float* base = g_feats + (size_t)t_idx[p] * NN * HH + q * 4;
    float4 s = make_float4(0.f, 0.f, 0.f, 0.f);
    int e = e0;
    for (; e + 4 <= e1; e += 4) {
        int i0 = dst_nodes[e], i1 = dst_nodes[e + 1];
        int i2 = dst_nodes[e + 2], i3 = dst_nodes[e + 3];
        float4 v0 = *(const float4*)(base + (size_t)i0 * HH);
        float4 v1 = *(const float4*)(base + (size_t)i1 * HH);
        float4 v2 = *(const float4*)(base + (size_t)i2 * HH);
        float4 v3 = *(const float4*)(base + (size_t)i3 * HH);
        s.x += v0.x + v1.x + v2.x + v3.x;
        s.y += v0.y + v1.y + v2.y + v3.y;
        s.z += v0.z + v1.z + v2.z + v3.z;
        s.w += v0.w + v1.w + v2.w + v3.w;
    }
    for (; e < e1; e++) {
        float4 v = *(const float4*)(base + (size_t)dst_nodes[e] * HH);
        s.x += v.x; s.y += v.y; s.z += v.z; s.w += v.w;
    }
    *(float4*)(g_dstf + (size_t)p * HH + q * 4) = s;
}

// ---------------- group / variant bookkeeping (atomic-free; group_id sorted) ----
__global__ void k_gbounds(const int* __restrict__ group_id) {
    int g = blockIdx.x * blockDim.x + threadIdx.x;
    if (g > GG) return;
    int lo = 0, hi = PP;
    while (lo < hi) {
        int mid = (lo + hi) >> 1;
        if (group_id[mid] < g) lo = mid + 1; else hi = mid;
    }
    g_gstart[g] = lo;
}

__global__ void k_group_seq() {
    int g = blockIdx.x * blockDim.x + threadIdx.x;
    if (g >= GG) return;
    int e0 = g_gstart[g], e1 = g_gstart[g + 1];
    double s0 = 0.0, s1 = 0.0;
    for (int p = e0; p < e1; p++) {
        s0 += (double)g_logprob[p * 2];
        s1 += (double)g_logprob[p * 2 + 1];
    }
    g_gsum[g * 2]     = s0;
    g_gsum[g * 2 + 1] = s1;
}

__global__ void k_var_starts(const int* __restrict__ vg) {
    int g = blockIdx.x * blockDim.x + threadIdx.x;
    if (g >= GG) return;
    int v = vg[g];
    if (g == 0 || vg[g - 1] != v) g_vstart[v] = g;
}

__global__ void k_within(const int* __restrict__ vg) {
    int v = blockIdx.x * blockDim.x + threadIdx.x;
    if (v >= VV) return;
    int g = g_vstart[v];
    if (g < 0) return;
    double r0 = 0.0, r1 = 0.0;
    while (g < GG && vg[g] == v) {
        r0 += g_gsum[g * 2];
        r1 += g_gsum[g * 2 + 1];
        g_within[g * 2]     = (float)r0;
        g_within[g * 2 + 1] = (float)r1;
        g++;
    }
}

__global__ void k_logc(const float* __restrict__ counts) {
    __shared__ double red[8];
    double s = 0.0;
    for (int v = threadIdx.x; v < VV; v += blockDim.x) s += (double)counts[v];
#pragma unroll
    for (int o = 16; o; o >>= 1) s += __shfl_down_sync(0xffffffffu, s, o);
    if ((threadIdx.x & 31) == 0) red[threadIdx.x >> 5] = s;
    __syncthreads();
    double tot = 0.0;
#pragma unroll
    for (int i = 0; i < 8; i++) tot += red[i];
    for (int v = threadIdx.x; v < VV; v += blockDim.x)
        g_logc[v] = logf((float)((double)counts[v] / tot));
}

__global__ void k_finalize(const int* __restrict__ group_id, const int* __restrict__ vg,
                           const int* __restrict__ place_idx, float* __restrict__ out) {
    int idx = blockIdx.x * blockDim.x + threadIdx.x;
    if (idx >= PP * 2) return;
    int p = idx >> 1, o = idx & 1;
    int g = group_id[p];
    float add = g_logprob[idx] + g_within[g * 2 + o] + g_logc[vg[g]];
    atomicAdd(&out[place_idx[p] * 2 + o], add);
}

// ---------------- host launch ----------------
extern "C" void kernel_launch(void* const* d_in, const int* in_sizes, int n_in,
                              void* d_out, int out_size) {
    const float* x      = (const float*)d_in[0];
    const float* Wes    = (const float*)d_in[1];
    const float* Wen    = (const float*)d_in[2];
    const float* benc   = (const float*)d_in[3];
    const float* W2s    = (const float*)d_in[4];
    const float* W2n    = (const float*)d_in[5];
    const float* b2     = (const float*)d_in[6];
    const float* Wd1    = (const float*)d_in[7];
    const float* bd1    = (const float*)d_in[8];
    const float* Wd2    = (const float*)d_in[9];
    const float* bd2    = (const float*)d_in[10];
    const float* counts = (const float*)d_in[11];
    const int* edge_src = (const int*)d_in[12];
    const int* edge_dst = (const int*)d_in[13];
    const int* place_idx = (const int*)d_in[14];
    const int* src_idx   = (const int*)d_in[15];
    const int* t_idx     = (const int*)d_in[16];
    const int* dst_nodes = (const int*)d_in[17];
    const int* dst_seg   = (const int*)d_in[18];
    const int* group_id  = (const int*)d_in[19];
    const int* vg        = (const int*)d_in[20];
    float* out = (float*)d_out;

    void *p_deg, *p_vstart, *p_feats, *p_agg;
    cudaGetSymbolAddress(&p_deg, g_deg);
    cudaGetSymbolAddress(&p_vstart, g_vstart);
    cudaGetSymbolAddress(&p_feats, g_feats);
    cudaGetSymbolAddress(&p_agg, g_agg);
    float* feats = (float*)p_feats;
    float* agg   = (float*)p_agg;

    cudaFuncSetAttribute(k_gemm_dec, cudaFuncAttributeMaxDynamicSharedMemorySize, DEC_SMEM);

    // --- CSR build ---
    cudaMemsetAsync(p_deg, 0, NN * sizeof(int));
    k_count_deg<<<(EE + 255) / 256, 256>>>(edge_dst);
    k_scan<<<1, 1024>>>();
    k_fill<<<(EE + 255) / 256, 256>>>(edge_src, edge_dst);

    // --- independent prep (no feats dependency) ---
    k_dst_bounds<<<(PP + 256) / 256, 256>>>(dst_seg);
    k_gbounds<<<(GG + 256) / 256, 256>>>(group_id);
    cudaMemsetAsync(p_vstart, 0xFF, VV * sizeof(int));
    k_var_starts<<<(GG + 255) / 256, 256>>>(vg);
    k_logc<<<1, 256>>>(counts);

    dim3 gemmGridN(1, (NN + 127) / 128);

    // --- encoder ---
    k_aggregate4<FINF><<<(NN + 15) / 16, dim3(16, 16)>>>(x);
    k_sgemm_dual<<<gemmGridN, 256>>>(x, FINF, agg, FINF, Wes, Wen, benc,
                                     feats, NN, HH);

    // --- T recurrent steps ---
    for (int t = 1; t <= TT; t++) {
        const float* hp = feats + (size_t)(t - 1) * NN * HH;
        float* hn = feats + (size_t)t * NN * HH;
        k_aggregate4<HH><<<(NN + 7) / 8, dim3(32, 8)>>>(hp);
        k_sgemm_dual<<<gemmGridN, 256>>>(hp, HH, agg, HH, W2s, W2n, b2,
                                         hn, NN, HH);
    }

    // --- dst segment sums ---
    k_dst_sum<<<(PP * 32 + 255) / 256, 256>>>(dst_nodes, t_idx);

    // --- fused decoder GEMM (3 col-blocks/CTA, BK=32) + logits + log_softmax ---
    k_gemm_dec<<<(PP + 127) / 128, 256, DEC_SMEM>>>(Wd1, bd1, Wd2, bd2,
                                                    place_idx, src_idx, t_idx);

    // --- group / variant running sums (atomic-free) ---
    k_group_seq<<<(GG + 255) / 256, 256>>>();
    k_within<<<(VV + 255) / 256, 256>>>(vg);

    // --- output scatter ---
    cudaMemsetAsync(d_out, 0, (size_t)out_size * sizeof(float));
    k_finalize<<<(PP * 2 + 255) / 256, 256>>>(group_id, vg, place_idx, out);
}

// round 16
// speedup vs baseline: 1.0980x; 1.0980x over previous
#include <cuda_runtime.h>
#include <math.h>
#include <stdint.h>

#define NN  50000
#define FINF 64
#define HH  128
#define EE  800000
#define TT  8
#define PP  250000
#define DD  500000
#define GG  20000
#define VV  2000
#define CATW 384

// ---------------- scratch (device globals; no allocation allowed) ----------------
__device__ __align__(16) float  g_feats[(size_t)(TT + 1) * NN * HH];
__device__ __align__(16) float  g_agg[(size_t)NN * HH];
__device__ __align__(16) float  g_dstf[(size_t)PP * HH];
__device__ float  g_logprob[PP * 2];
__device__ double g_gsum[GG * 2];
__device__ float  g_within[GG * 2];
__device__ int    g_deg[NN];
__device__ float  g_invdeg[NN];
__device__ int    g_rowptr[NN + 1];
__device__ int    g_cursor[NN];
__device__ int    g_csr[EE];
__device__ int    g_vstart[VV];
__device__ float  g_logc[VV];
__device__ int    g_dstart[PP + 1];
__device__ int    g_gstart[GG + 1];

// ---------------- packed fp32x2 helpers ----------------
__device__ __forceinline__ unsigned long long pk2(float lo, float hi) {
    unsigned long long r;
    asm("mov.b64 %0, {%1, %2};" : "=l"(r) : "f"(lo), "f"(hi));
    return r;
}
__device__ __forceinline__ void upk2(unsigned long long v, float& lo, float& hi) {
    asm("mov.b64 {%0, %1}, %2;" : "=f"(lo), "=f"(hi) : "l"(v));
}
#define FFMA2(c, a, b) \
    asm("fma.rn.f32x2 %0, %1, %2, %3;" : "=l"(c) : "l"(a), "l"(b), "l"(c))

// ---------------- cp.async helpers ----------------
__device__ __forceinline__ void cp_async16(void* smem_ptr, const void* gptr) {
    uint32_t sa = (uint32_t)__cvta_generic_to_shared(smem_ptr);
    asm volatile("cp.async.ca.shared.global [%0], [%1], 16;" :: "r"(sa), "l"(gptr));
}
#define CP_COMMIT() asm volatile("cp.async.commit_group;" ::: "memory")
#define CP_WAIT0()  asm volatile("cp.async.wait_group 0;" ::: "memory")

#define BSTR 132

// per-k-step compute (round-9 proven form)
#define K_STEP(Asb, Bsb, kk)                                                    \
    do {                                                                        \
        float4 a0 = *(const float4*)&(Asb)[kk][rowBase];                        \
        float4 a1 = *(const float4*)&(Asb)[kk][rowBase + 4];                    \
        float4 b0 = *(const float4*)&(Bsb)[kk][colBase];                        \
        float4 b1 = *(const float4*)&(Bsb)[kk][colBase + 4];                    \
        unsigned long long rbp[4];                                              \
        rbp[0] = pk2(b0.x, b0.y);                                               \
        rbp[1] = pk2(b0.z, b0.w);                                               \
        rbp[2] = pk2(b1.x, b1.y);                                               \
        rbp[3] = pk2(b1.z, b1.w);                                               \
        float ra[8] = {a0.x, a0.y, a0.z, a0.w, a1.x, a1.y, a1.z, a1.w};         \
        _Pragma("unroll")                                                       \
        for (int i = 0; i < 8; i++) {                                           \
            unsigned long long rai = pk2(ra[i], ra[i]);                         \
            _Pragma("unroll")                                                   \
            for (int j = 0; j < 4; j++) FFMA2(acc2[i][j], rai, rbp[j]);         \
        }                                                                       \
    } while (0)

// ---------------- CSR build ----------------
__global__ void k_count_deg(const int* __restrict__ edge_dst) {
    int e = blockIdx.x * blockDim.x + threadIdx.x;
    if (e < EE) atomicAdd(&g_deg[edge_dst[e]], 1);
}

__global__ void k_scan() {
    __shared__ int warpsum[32];
    __shared__ int s_carry;
    if (threadIdx.x == 0) s_carry = 0;
    __syncthreads();
    int lane = threadIdx.x & 31, w = threadIdx.x >> 5;
    for (int base = 0; base < NN; base += 1024) {
        int i = base + threadIdx.x;
        int v = (i < NN) ? g_deg[i] : 0;
        int s = v;
#pragma unroll
        for (int o = 1; o < 32; o <<= 1) {
            int t = __shfl_up_sync(0xffffffffu, s, o);
            if (lane >= o) s += t;
        }
        if (lane == 31) warpsum[w] = s;
        __syncthreads();
        if (w == 0) {
            int ws = warpsum[lane];
#pragma unroll
            for (int o = 1; o < 32; o <<= 1) {
                int t = __shfl_up_sync(0xffffffffu, ws, o);
                if (lane >= o) ws += t;
            }
            warpsum[lane] = ws;
        }
        __syncthreads();
        int incl = s + (w > 0 ? warpsum[w - 1] : 0) + s_carry;
        if (i < NN) {
            g_rowptr[i + 1] = incl;
            g_cursor[i] = incl - v;
            g_invdeg[i] = 1.0f / (float)(v > 1 ? v : 1);
            if (i == 0) g_rowptr[0] = 0;
        }
        __syncthreads();
        if (threadIdx.x == 1023) s_carry = incl;
        __syncthreads();
    }
}

__global__ void k_fill(const int* __restrict__ edge_src, const int* __restrict__ edge_dst) {
    int e = blockIdx.x * blockDim.x + threadIdx.x;
    if (e >= EE) return;
    int pos = atomicAdd(&g_cursor[edge_dst[e]], 1);
    g_csr[pos] = edge_src[e];
}

// ---------------- mean aggregation (atomic-free via CSR, float4) ----------------
template <int F>
__global__ void k_aggregate4(const float* __restrict__ h) {
    int node = blockIdx.x * blockDim.y + threadIdx.y;
    if (node >= NN) return;
    int f4 = threadIdx.x;
    int e0 = g_rowptr[node], e1 = g_rowptr[node + 1];
    float4 s = make_float4(0.f, 0.f, 0.f, 0.f);
    for (int e = e0; e < e1; e++) {
        int src = g_csr[e];
        float4 v = *(const float4*)(h + (size_t)src * F + f4 * 4);
        s.x += v.x; s.y += v.y; s.z += v.z; s.w += v.w;
    }
    float id = g_invdeg[node];
    s.x *= id; s.y *= id; s.z *= id; s.w *= id;
    *(float4*)(g_agg + (size_t)node * F + f4 * 4) = s;
}

// ---------------- MP GEMM: C = relu(A1@W1 + A2@W2 + bias), BK=16, cp.async B ----
__global__ __launch_bounds__(256) void k_sgemm_dual(
    const float* __restrict__ A1, int K1,
    const float* __restrict__ A2, int K2,
    const float* __restrict__ W1, const float* __restrict__ W2,
    const float* __restrict__ bias,
    float* __restrict__ C, int M, int NC)
{
    __shared__ __align__(16) float As[2][16][BSTR];
    __shared__ __align__(16) float Bs[2][16][BSTR];
    int tid = threadIdx.x;
    int rowBlock = blockIdx.y * 128;
    int colBlock = blockIdx.x * 128;
    int tx = tid & 15, ty = tid >> 4;
    int rowBase = ty * 8, colBase = tx * 8;

    int la_r[2], la_k[2], lb_k[2], lb_n[2];
#pragma unroll
    for (int i = 0; i < 2; i++) {
        int slot = tid * 2 + i;
        la_r[i] = slot >> 2;
        la_k[i] = (slot & 3) * 4;
        lb_k[i] = slot >> 5;
        lb_n[i] = (slot & 31) * 4;
    }

    unsigned long long acc2[8][4];
#pragma unroll
    for (int i = 0; i < 8; i++)
#pragma unroll
        for (int j = 0; j < 4; j++) acc2[i][j] = 0ull;

    int nt1 = K1 >> 4;
    int nt = nt1 + (K2 >> 4);

    // initial tile: B via cp.async, A via registers
#pragma unroll
    for (int i = 0; i < 2; i++)
        cp_async16(&Bs[0][lb_k[i]][lb_n[i]], W1 + (size_t)lb_k[i] * NC + colBlock + lb_n[i]);
    CP_COMMIT();
    float4 av[2];
#pragma unroll
    for (int i = 0; i < 2; i++) {
        int gm = rowBlock + la_r[i];
        av[i] = (gm < M) ? *(const float4*)(A1 + (size_t)gm * K1 + la_k[i])
                         : make_float4(0.f, 0.f, 0.f, 0.f);
        As[0][la_k[i] + 0][la_r[i]] = av[i].x;
        As[0][la_k[i] + 1][la_r[i]] = av[i].y;
        As[0][la_k[i] + 2][la_r[i]] = av[i].z;
        As[0][la_k[i] + 3][la_r[i]] = av[i].w;
    }
    CP_WAIT0();
    __syncthreads();

    int s = 0;
#pragma unroll 1
    for (int t = 0; t < nt; t++) {
        int sn = s ^ 1;
        if (t + 1 < nt) {
            int tn = t + 1;
            const float* A; const float* W; int K; int k0;
            if (tn < nt1) { A = A1; W = W1; K = K1; k0 = tn * 16; }
            else          { A = A2; W = W2; K = K2; k0 = (tn - nt1) * 16; }
#pragma unroll
            for (int i = 0; i < 2; i++)
                cp_async16(&Bs[sn][lb_k[i]][lb_n[i]],
                           W + (size_t)(k0 + lb_k[i]) * NC + colBlock + lb_n[i]);
            CP_COMMIT();
#pragma unroll
            for (int i = 0; i < 2; i++) {
                int gm = rowBlock + la_r[i];
                av[i] = (gm < M) ? *(const float4*)(A + (size_t)gm * K + k0 + la_k[i])
                                 : make_float4(0.f, 0.f, 0.f, 0.f);
            }
        }
#pragma unroll
        for (int k = 0; k < 16; k++) K_STEP(As[s], Bs[s], k);
        if (t + 1 < nt) {
#pragma unroll
            for (int i = 0; i < 2; i++) {
                As[sn][la_k[i] + 0][la_r[i]] = av[i].x;
                As[sn][la_k[i] + 1][la_r[i]] = av[i].y;
                As[sn][la_k[i] + 2][la_r[i]] = av[i].z;
                As[sn][la_k[i] + 3][la_r[i]] = av[i].w;
            }
            CP_WAIT0();
        }
        __syncthreads();
        s ^= 1;
    }

    float4 bb0 = *(const float4*)(bias + colBlock + colBase);
    float4 bb1 = *(const float4*)(bias + colBlock + colBase + 4);
    float bbs[8] = {bb0.x, bb0.y, bb0.z, bb0.w, bb1.x, bb1.y, bb1.z, bb1.w};
#pragma unroll
    for (int i = 0; i < 8; i++) {
        int gm = rowBlock + rowBase + i;
        if (gm >= M) continue;
        float o[8];
#pragma unroll
        for (int j = 0; j < 4; j++) upk2(acc2[i][j], o[j * 2], o[j * 2 + 1]);
#pragma unroll
        for (int j = 0; j < 8; j++) o[j] = fmaxf(o[j] + bbs[j], 0.f);
        float* cp = C + (size_t)gm * NC + colBlock + colBase;
        *(float4*)cp       = make_float4(o[0], o[1], o[2], o[3]);
        *(float4*)(cp + 4) = make_float4(o[4], o[5], o[6], o[7]);
    }
}

// ---------------- fused decoder: 3 col-blocks/CTA, BK=16, cp.async B ------------
__global__ __launch_bounds__(256) void k_gemm_dec(
    const float* __restrict__ Wd1, const float* __restrict__ bd1,
    const float* __restrict__ Wd2, const float* __restrict__ bd2,
    const int* __restrict__ place_idx, const int* __restrict__ src_idx,
    const int* __restrict__ t_idx)
{
    extern __shared__ __align__(16) float dsm[];
    float (*As)[16][BSTR] = (float (*)[16][BSTR])dsm;
    float (*Bs)[16][BSTR] = (float (*)[16][BSTR])(dsm + 2 * 16 * BSTR);
    float2 (*red)[17] = (float2 (*)[17])(dsm + 4 * 16 * BSTR);

    int tid = threadIdx.x;
    int rowBlock = blockIdx.x * 128;
    int tx = tid & 15, ty = tid >> 4;
    int rowBase = ty * 8, colBase = tx * 8;

    int la_r[2], la_k[2], lb_k[2], lb_n[2];
#pragma unroll
    for (int i = 0; i < 2; i++) {
        int slot = tid * 2 + i;
        la_r[i] = slot >> 2;
        la_k[i] = (slot & 3) * 4;
        lb_k[i] = slot >> 5;
        lb_n[i] = (slot & 31) * 4;
    }

#pragma unroll
    for (int i = tid; i < 128 * 17; i += 256)
        ((float2*)red)[i] = make_float2(0.f, 0.f);

    const float* ap[2][3];
    bool mokL[2];
#pragma unroll
    for (int i = 0; i < 2; i++) {
        int p = rowBlock + la_r[i];
        mokL[i] = p < PP;
        int pidx = mokL[i] ? p : 0;
        int t = __ldg(t_idx + pidx);
        ap[i][0] = g_feats + ((size_t)t * NN + __ldg(place_idx + pidx)) * HH;
        ap[i][1] = g_feats + ((size_t)t * NN + __ldg(src_idx + pidx)) * HH;
        ap[i][2] = g_dstf + (size_t)pidx * HH;
    }

    const int nt = CATW / 16;  // 24

#pragma unroll 1
    for (int cb = 0; cb < 3; cb++) {
        int colBlock = cb * 128;

        unsigned long long acc2[8][4];
#pragma unroll
        for (int i = 0; i < 8; i++)
#pragma unroll
            for (int j = 0; j < 4; j++) acc2[i][j] = 0ull;

#pragma unroll
        for (int i = 0; i < 2; i++)
            cp_async16(&Bs[0][lb_k[i]][lb_n[i]],
                       Wd1 + (size_t)lb_k[i] * CATW + colBlock + lb_n[i]);
        CP_COMMIT();
        float4 av[2];
#pragma unroll
        for (int i = 0; i < 2; i++) {
            av[i] = mokL[i] ? *(const float4*)(ap[i][0] + la_k[i])
                            : make_float4(0.f, 0.f, 0.f, 0.f);
            As[0][la_k[i] + 0][la_r[i]] = av[i].x;
            As[0][la_k[i] + 1][la_r[i]] = av[i].y;
            As[0][la_k[i] + 2][la_r[i]] = av[i].z;
            As[0][la_k[i] + 3][la_r[i]] = av[i].w;
        }
        CP_WAIT0();
        __syncthreads();

        int s = 0;
#pragma unroll 1
        for (int t = 0; t < nt; t++) {
            int sn = s ^ 1;
            if (t + 1 < nt) {
                int k0 = (t + 1) * 16;
                int seg = k0 >> 7, koff = k0 & 127;
#pragma unroll
                for (int i = 0; i < 2; i++)
                    cp_async16(&Bs[sn][lb_k[i]][lb_n[i]],
                               Wd1 + (size_t)(k0 + lb_k[i]) * CATW + colBlock + lb_n[i]);
                CP_COMMIT();
#pragma unroll
                for (int i = 0; i < 2; i++)
                    av[i] = mokL[i] ? *(const float4*)(ap[i][seg] + koff + la_k[i])
                                    : make_float4(0.f, 0.f, 0.f, 0.f);
            }
#pragma unroll
            for (int k = 0; k < 16; k++) K_STEP(As[s], Bs[s], k);
            if (t + 1 < nt) {
#pragma unroll
                for (int i = 0; i < 2; i++) {
                    As[sn][la_k[i] + 0][la_r[i]] = av[i].x;
                    As[sn][la_k[i] + 1][la_r[i]] = av[i].y;
                    As[sn][la_k[i] + 2][la_r[i]] = av[i].z;
                    As[sn][la_k[i] + 3][la_r[i]] = av[i].w;
                }
                CP_WAIT0();
            }
            __syncthreads();
            s ^= 1;
        }

        float4 bb0 = *(const float4*)(bd1 + colBlock + colBase);
        float4 bb1 = *(const float4*)(bd1 + colBlock + colBase + 4);
        float bbs[8] = {bb0.x, bb0.y, bb0.z, bb0.w, bb1.x, bb1.y, bb1.z, bb1.w};
        float w20[8], w21[8];
#pragma unroll
        for (int j = 0; j < 8; j++) {
            float2 w = *(const float2*)(Wd2 + (colBlock + colBase + j) * 2);
            w20[j] = w.x; w21[j] = w.y;
        }
#pragma unroll
        for (int i = 0; i < 8; i++) {
            float o[8];
#pragma unroll
            for (int j = 0; j < 4; j++) upk2(acc2[i][j], o[j * 2], o[j * 2 + 1]);
            float pa0 = 0.f, pa1 = 0.f;
#pragma unroll
            for (int j = 0; j < 8; j++) {
                float h = fmaxf(o[j] + bbs[j], 0.f);
                pa0 += h * w20[j];
                pa1 += h * w21[j];
            }
            float2 cur = red[rowBase + i][tx];
            red[rowBase + i][tx] = make_float2(cur.x + pa0, cur.y + pa1);
        }
        __syncthreads();
    }

    if (tid < 128) {
        int p = rowBlock + tid;
        if (p < PP) {
            float s0 = 0.f, s1 = 0.f;
#pragma unroll
            for (int c = 0; c < 16; c++) {
                float2 v = red[tid][c];
                s0 += v.x; s1 += v.y;
            }
            float a0 = s0 + bd2[0];
            float a1 = s1 + bd2[1];
            float m = fmaxf(a0, a1);
            float lse = m + logf(expf(a0 - m) + expf(a1 - m));
            g_logprob[p * 2]     = a0 - lse;
            g_logprob[p * 2 + 1] = a1 - lse;
        }
    }
}

#define DEC_SMEM ((4 * 16 * BSTR + 128 * 17 * 2) * 4)

// ---------------- dst segment-sum (atomic-free; dst_seg is sorted) ----------------
__global__ void k_dst_bounds(const int* __restrict__ dst_seg) {
    int p = blockIdx.x * blockDim.x + threadIdx.x;
    if (p > PP) return;
    int lo = 0, hi = DD;
    while (lo < hi) {
        int mid = (lo + hi) >> 1;
        if (dst_seg[mid] < p) lo = mid + 1; else hi = mid;
    }
    g_dstart[p] = lo;
}

__global__ void k_dst_sum(const int* __restrict__ dst_nodes, const int* __restrict__ t_idx) {
    int idx = blockIdx.x * blockDim.x + threadIdx.x;
    if (idx >= PP * 32) return;
    int p = idx >> 5, q = idx & 31;
    int e0 = g_dstart[p], e1 = g_dstart[p + 1];
    const float* base = g_feats + (size_t)t_idx[p] * NN * HH + q * 4;
    float4 s = make_float4(0.f, 0.f, 0.f, 0.f);
    int e = e0;
    for (; e + 4 <= e1; e += 4) {
        int i0 = dst_nodes[e], i1 = dst_nodes[e + 1];
        int i2 = dst_nodes[e + 2], i3 = dst_nodes[e + 3];
        float4 v0 = *(const float4*)(base + (size_t)i0 * HH);
        float4 v1 = *(const float4*)(base + (size_t)i1 * HH);
        float4 v2 = *(const float4*)(base + (size_t)i2 * HH);
        float4 v3 = *(const float4*)(base + (size_t)i3 * HH);
        s.x += v0.x + v1.x + v2.x + v3.x;
        s.y += v0.y + v1.y + v2.y + v3.y;
        s.z += v0.z + v1.z + v2.z + v3.z;
        s.w += v0.w + v1.w + v2.w + v3.w;
    }
    for (; e < e1; e++) {
        float4 v = *(const float4*)(base + (size_t)dst_nodes[e] * HH);
        s.x += v.x; s.y += v.y; s.z += v.z; s.w += v.w;
    }
    *(float4*)(g_dstf + (size_t)p * HH + q * 4) = s;
}

// ---------------- group / variant bookkeeping (atomic-free; group_id sorted) ----
__global__ void k_gbounds(const int* __restrict__ group_id) {
    int g = blockIdx.x * blockDim.x + threadIdx.x;
    if (g > GG) return;
    int lo = 0, hi = PP;
    while (lo < hi) {
        int mid = (lo + hi) >> 1;
        if (group_id[mid] < g) lo = mid + 1; else hi = mid;
    }
    g_gstart[g] = lo;
}

__global__ void k_group_seq() {
    int g = blockIdx.x * blockDim.x + threadIdx.x;
    if (g >= GG) return;
    int e0 = g_gstart[g], e1 = g_gstart[g + 1];
    double s0 = 0.0, s1 = 0.0;
    for (int p = e0; p < e1; p++) {
        s0 += (double)g_logprob[p * 2];
        s1 += (double)g_logprob[p * 2 + 1];
    }
    g_gsum[g * 2]     = s0;
    g_gsum[g * 2 + 1] = s1;
}

__global__ void k_var_starts(const int* __restrict__ vg) {
    int g = blockIdx.x * blockDim.x + threadIdx.x;
    if (g >= GG) return;
    int v = vg[g];
    if (g == 0 || vg[g - 1] != v) g_vstart[v] = g;
}

__global__ void k_within(const int* __restrict__ vg) {
    int v = blockIdx.x * blockDim.x + threadIdx.x;
    if (v >= VV) return;
    int g = g_vstart[v];
    if (g < 0) return;
    double r0 = 0.0, r1 = 0.0;
    while (g < GG && vg[g] == v) {
        r0 += g_gsum[g * 2];
        r1 += g_gsum[g * 2 + 1];
        g_within[g * 2]     = (float)r0;
        g_within[g * 2 + 1] = (float)r1;
        g++;
    }
}

__global__ void k_logc(const float* __restrict__ counts) {
    __shared__ double red[8];
    double s = 0.0;
    for (int v = threadIdx.x; v < VV; v += blockDim.x) s += (double)counts[v];
#pragma unroll
    for (int o = 16; o; o >>= 1) s += __shfl_down_sync(0xffffffffu, s, o);
    if ((threadIdx.x & 31) == 0) red[threadIdx.x >> 5] = s;
    __syncthreads();
    double tot = 0.0;
#pragma unroll
    for (int i = 0; i < 8; i++) tot += red[i];
    for (int v = threadIdx.x; v < VV; v += blockDim.x)
        g_logc[v] = logf((float)((double)counts[v] / tot));
}

__global__ void k_finalize(const int* __restrict__ group_id, const int* __restrict__ vg,
                           const int* __restrict__ place_idx, float* __restrict__ out) {
    int idx = blockIdx.x * blockDim.x + threadIdx.x;
    if (idx >= PP * 2) return;
    int p = idx >> 1, o = idx & 1;
    int g = group_id[p];
    float add = g_logprob[idx] + g_within[g * 2 + o] + g_logc[vg[g]];
    atomicAdd(&out[place_idx[p] * 2 + o], add);
}

// ---------------- host launch ----------------
extern "C" void kernel_launch(void* const* d_in, const int* in_sizes, int n_in,
                              void* d_out, int out_size) {
    const float* x      = (const float*)d_in[0];
    const float* Wes    = (const float*)d_in[1];
    const float* Wen    = (const float*)d_in[2];
    const float* benc   = (const float*)d_in[3];
    const float* W2s    = (const float*)d_in[4];
    const float* W2n    = (const float*)d_in[5];
    const float* b2     = (const float*)d_in[6];
    const float* Wd1    = (const float*)d_in[7];
    const float* bd1    = (const float*)d_in[8];
    const float* Wd2    = (const float*)d_in[9];
    const float* bd2    = (const float*)d_in[10];
    const float* counts = (const float*)d_in[11];
    const int* edge_src = (const int*)d_in[12];
    const int* edge_dst = (const int*)d_in[13];
    const int* place_idx = (const int*)d_in[14];
    const int* src_idx   = (const int*)d_in[15];
    const int* t_idx     = (const int*)d_in[16];
    const int* dst_nodes = (const int*)d_in[17];
    const int* dst_seg   = (const int*)d_in[18];
    const int* group_id  = (const int*)d_in[19];
    const int* vg        = (const int*)d_in[20];
    float* out = (float*)d_out;

    void *p_deg, *p_vstart, *p_feats, *p_agg;
    cudaGetSymbolAddress(&p_deg, g_deg);
    cudaGetSymbolAddress(&p_vstart, g_vstart);
    cudaGetSymbolAddress(&p_feats, g_feats);
    cudaGetSymbolAddress(&p_agg, g_agg);
    float* feats = (float*)p_feats;
    float* agg   = (float*)p_agg;

    cudaFuncSetAttribute(k_gemm_dec, cudaFuncAttributeMaxDynamicSharedMemorySize, DEC_SMEM);

    // --- CSR build ---
    cudaMemsetAsync(p_deg, 0, NN * sizeof(int));
    k_count_deg<<<(EE + 255) / 256, 256>>>(edge_dst);
    k_scan<<<1, 1024>>>();
    k_fill<<<(EE + 255) / 256, 256>>>(edge_src, edge_dst);

    // --- independent prep (no feats dependency) ---
    k_dst_bounds<<<(PP + 256) / 256, 256>>>(dst_seg);
    k_gbounds<<<(GG + 256) / 256, 256>>>(group_id);
    cudaMemsetAsync(p_vstart, 0xFF, VV * sizeof(int));
    k_var_starts<<<(GG + 255) / 256, 256>>>(vg);
    k_logc<<<1, 256>>>(counts);

    dim3 gemmGridN(1, (NN + 127) / 128);

    // --- encoder ---
    k_aggregate4<FINF><<<(NN + 15) / 16, dim3(16, 16)>>>(x);
    k_sgemm_dual<<<gemmGridN, 256>>>(x, FINF, agg, FINF, Wes, Wen, benc,
                                     feats, NN, HH);

    // --- T recurrent steps ---
    for (int t = 1; t <= TT; t++) {
        const float* hp = feats + (size_t)(t - 1) * NN * HH;
        float* hn = feats + (size_t)t * NN * HH;
        k_aggregate4<HH><<<(NN + 7) / 8, dim3(32, 8)>>>(hp);
        k_sgemm_dual<<<gemmGridN, 256>>>(hp, HH, agg, HH, W2s, W2n, b2,
                                         hn, NN, HH);
    }

    // --- dst segment sums ---
    k_dst_sum<<<(PP * 32 + 255) / 256, 256>>>(dst_nodes, t_idx);

    // --- fused decoder GEMM (3 col-blocks/CTA, BK=16) + logits + log_softmax ---
    k_gemm_dec<<<(PP + 127) / 128, 256, DEC_SMEM>>>(Wd1, bd1, Wd2, bd2,
                                                    place_idx, src_idx, t_idx);

    // --- group / variant running sums (atomic-free) ---
    k_group_seq<<<(GG + 255) / 256, 256>>>();
    k_within<<<(VV + 255) / 256, 256>>>(vg);

    // --- output scatter ---
    cudaMemsetAsync(d_out, 0, (size_t)out_size * sizeof(float));
    k_finalize<<<(PP * 2 + 255) / 256, 256>>>(group_id, vg, place_idx, out);
}